// round 2
// baseline (speedup 1.0000x reference)
#include <cuda_runtime.h>
#include <cstdint>
#include <cstddef>

// MultiAgentSEPSNetwork: 8 agents x (4096,256)->1024->1024->512 MLP,
// per-agent network selected by seps_idx. Only the selected net is computed.
//
// Round 2: fix seps_idx dtype (JAX canonicalizes int64 -> int32; reading it as
// long long paired elements into a huge index -> OOB weight pointer -> the R1
// illegal memory access). Index is now read as int32 and masked to [0,3].
// GEMM core unchanged: 3xTF32-compensated mma.sync, 3 launches.

namespace seps {

constexpr int NA = 8;
constexpr int NE = 4096;

// Scratch for inter-layer activations (device globals: no runtime allocs).
__device__ float g_h1[(size_t)NA * NE * 1024];
__device__ float g_h2[(size_t)NA * NE * 1024];

__device__ __forceinline__ uint32_t tf32_rna(float x) {
    uint32_t r;
    asm("cvt.rna.tf32.f32 %0, %1;" : "=r"(r) : "f"(x));
    return r;
}

__device__ __forceinline__ void mma8(float* c, const uint32_t* a, const uint32_t* b) {
    asm volatile(
        "mma.sync.aligned.m16n8k8.row.col.f32.tf32.tf32.f32 "
        "{%0,%1,%2,%3}, {%4,%5,%6,%7}, {%8,%9}, {%0,%1,%2,%3};"
        : "+f"(c[0]), "+f"(c[1]), "+f"(c[2]), "+f"(c[3])
        : "r"(a[0]), "r"(a[1]), "r"(a[2]), "r"(a[3]),
          "r"(b[0]), "r"(b[1]));
}

// Y[agent] = act( X[agent] @ W[seps_idx[agent]] + bias[seps_idx[agent]] )
// X: [NA, NE, K]   W: [S, K, N]   bias: [S, N]   Y: [NA, NE, N]
// CTA tile: 128(M) x 128(N), KT=16. 8 warps, each 32x64 via m16n8k8.
template<int K, int N, bool RELU>
__global__ __launch_bounds__(256, 2)
void gemm3x_kernel(const float* __restrict__ X, const float* __restrict__ W,
                   const float* __restrict__ bias,
                   const int* __restrict__ sidx,
                   float* __restrict__ Y)
{
    constexpr int KT  = 16;
    constexpr int AS  = KT + 4;    // A smem stride (pad: conflict-free frag loads)
    constexpr int BSD = 128 + 4;   // B smem stride (pad: conflict-free frag loads)

    __shared__ float sAh[128 * AS];
    __shared__ float sAl[128 * AS];
    __shared__ float sBh[KT * BSD];
    __shared__ float sBl[KT * BSD];

    const int tid  = threadIdx.x;
    const int lane = tid & 31;
    const int warp = tid >> 5;
    const int g = lane >> 2;   // group id (0..7)
    const int t = lane & 3;    // thread-in-group (0..3)
    const int wm = (warp & 3) * 32;  // warp M offset in CTA tile
    const int wn = (warp >> 2) * 64; // warp N offset in CTA tile

    const int agent = blockIdx.z;
    const int m0 = blockIdx.y * 128;
    const int n0 = blockIdx.x * 128;
    // seps_idx arrives as int32 (JAX x64-disabled canonicalization). Mask to
    // the valid S=4 range so a dtype surprise can never produce a wild pointer.
    const int s = sidx[agent] & 3;

    const float* Xa = X    + (size_t)agent * NE * K;
    const float* Ws = W    + (size_t)s * K * N;
    const float* bs = bias + (size_t)s * N;
    float*       Ya = Y    + (size_t)agent * NE * N;

    float acc[2][8][4];
    #pragma unroll
    for (int mi = 0; mi < 2; ++mi)
        #pragma unroll
        for (int ni = 0; ni < 8; ++ni)
            #pragma unroll
            for (int j = 0; j < 4; ++j) acc[mi][ni][j] = 0.f;

    // Global->smem load mapping (256 threads, 2 passes each for A and B).
    const int ar  = tid >> 2;          // A row 0..63 (+64 on pass 1)
    const int ac  = (tid & 3) * 4;     // A col {0,4,8,12}
    const int brr = tid >> 5;          // B row 0..7 (+8 on pass 1)
    const int bc  = lane * 4;          // B col 0..124

    #pragma unroll 1
    for (int kt = 0; kt < K; kt += KT) {
        float4 av[2], bv[2];
        #pragma unroll
        for (int p = 0; p < 2; ++p) {
            av[p] = *reinterpret_cast<const float4*>(
                Xa + (size_t)(m0 + ar + p * 64) * K + kt + ac);
            bv[p] = *reinterpret_cast<const float4*>(
                Ws + (size_t)(kt + brr + p * 8) * N + n0 + bc);
        }
        __syncthreads();   // previous tile fully consumed
        #pragma unroll
        for (int p = 0; p < 2; ++p) {
            const float* a4 = reinterpret_cast<const float*>(&av[p]);
            const float* b4 = reinterpret_cast<const float*>(&bv[p]);
            const int abase = (ar + p * 64) * AS + ac;
            const int bbase = (brr + p * 8) * BSD + bc;
            #pragma unroll
            for (int j = 0; j < 4; ++j) {
                float x  = a4[j];
                float xh = __uint_as_float(tf32_rna(x));
                sAh[abase + j] = xh;
                sAl[abase + j] = x - xh;   // exact residual in fp32
                float w  = b4[j];
                float wh = __uint_as_float(tf32_rna(w));
                sBh[bbase + j] = wh;
                sBl[bbase + j] = w - wh;
            }
        }
        __syncthreads();

        #pragma unroll
        for (int ks = 0; ks < KT / 8; ++ks) {
            uint32_t ah[2][4], al[2][4];
            #pragma unroll
            for (int mi = 0; mi < 2; ++mi) {
                const int r  = wm + mi * 16 + g;
                const int c0 = ks * 8 + t;
                ah[mi][0] = __float_as_uint(sAh[(r    ) * AS + c0    ]);
                ah[mi][1] = __float_as_uint(sAh[(r + 8) * AS + c0    ]);
                ah[mi][2] = __float_as_uint(sAh[(r    ) * AS + c0 + 4]);
                ah[mi][3] = __float_as_uint(sAh[(r + 8) * AS + c0 + 4]);
                al[mi][0] = __float_as_uint(sAl[(r    ) * AS + c0    ]);
                al[mi][1] = __float_as_uint(sAl[(r + 8) * AS + c0    ]);
                al[mi][2] = __float_as_uint(sAl[(r    ) * AS + c0 + 4]);
                al[mi][3] = __float_as_uint(sAl[(r + 8) * AS + c0 + 4]);
            }
            #pragma unroll
            for (int ni = 0; ni < 8; ++ni) {
                uint32_t bh[2], bl[2];
                const int cc = wn + ni * 8 + g;
                const int rr = ks * 8 + t;
                bh[0] = __float_as_uint(sBh[(rr    ) * BSD + cc]);
                bh[1] = __float_as_uint(sBh[(rr + 4) * BSD + cc]);
                bl[0] = __float_as_uint(sBl[(rr    ) * BSD + cc]);
                bl[1] = __float_as_uint(sBl[(rr + 4) * BSD + cc]);
                #pragma unroll
                for (int mi = 0; mi < 2; ++mi) {
                    mma8(acc[mi][ni], ah[mi], bh);   // hi*hi
                    mma8(acc[mi][ni], ah[mi], bl);   // hi*lo
                    mma8(acc[mi][ni], al[mi], bh);   // lo*hi
                }
            }
        }
    }

    // Epilogue: bias (+ optional ReLU), float2 stores.
    #pragma unroll
    for (int mi = 0; mi < 2; ++mi) {
        const int r = m0 + wm + mi * 16 + g;
        #pragma unroll
        for (int ni = 0; ni < 8; ++ni) {
            const int ccol = n0 + wn + ni * 8 + 2 * t;
            const float2 bb = *reinterpret_cast<const float2*>(bs + ccol);
            float v0 = acc[mi][ni][0] + bb.x;
            float v1 = acc[mi][ni][1] + bb.y;
            float v2 = acc[mi][ni][2] + bb.x;
            float v3 = acc[mi][ni][3] + bb.y;
            if (RELU) {
                v0 = fmaxf(v0, 0.f); v1 = fmaxf(v1, 0.f);
                v2 = fmaxf(v2, 0.f); v3 = fmaxf(v3, 0.f);
            }
            *reinterpret_cast<float2*>(Ya + (size_t)(r    ) * N + ccol) = make_float2(v0, v1);
            *reinterpret_cast<float2*>(Ya + (size_t)(r + 8) * N + ccol) = make_float2(v2, v3);
        }
    }
}

} // namespace seps

extern "C" void kernel_launch(void* const* d_in, const int* in_sizes, int n_in,
                              void* d_out, int out_size)
{
    const float* x   = (const float*)d_in[0];   // [8, 4096, 256]
    const float* W1  = (const float*)d_in[1];   // [4, 256, 1024]
    const float* b1  = (const float*)d_in[2];   // [4, 1024]
    const float* W2  = (const float*)d_in[3];   // [4, 1024, 1024]
    const float* b2  = (const float*)d_in[4];   // [4, 1024]
    const float* W3  = (const float*)d_in[5];   // [4, 1024, 512]
    const float* b3  = (const float*)d_in[6];   // [4, 512]
    const int* sidx  = (const int*)d_in[7];     // [8] (int32 after JAX canonicalization)
    float* out = (float*)d_out;                 // [8, 4096, 512]

    float* h1 = nullptr;
    float* h2 = nullptr;
    cudaGetSymbolAddress((void**)&h1, seps::g_h1);
    cudaGetSymbolAddress((void**)&h2, seps::g_h2);

    const dim3 blk(256);
    // L1: K=256,  N=1024, ReLU
    seps::gemm3x_kernel<256, 1024, true ><<<dim3(8, 32, 8), blk>>>(x,  W1, b1, sidx, h1);
    // L2: K=1024, N=1024, ReLU
    seps::gemm3x_kernel<1024, 1024, true ><<<dim3(8, 32, 8), blk>>>(h1, W2, b2, sidx, h2);
    // L3: K=1024, N=512, no ReLU
    seps::gemm3x_kernel<1024, 512, false><<<dim3(4, 32, 8), blk>>>(h2, W3, b3, sidx, out);
}

// round 3
// speedup vs baseline: 1.3300x; 1.3300x over previous
#include <cuda_runtime.h>
#include <cstdint>
#include <cstddef>

// MultiAgentSEPSNetwork: 8 agents x (4096,256)->1024->1024->512 MLP,
// per-agent network selected by seps_idx (int32, masked to [0,3]).
//
// Round 3: R2 profile showed L1tex 82% (binding), tensor 47.7%.
//  - Smem now holds raw fp32 once; tf32 hi/lo split happens in registers
//    after LDS (halves STS+LDS traffic; cvt/sub go to idle fma/alu pipes).
//  - cp.async.cg double-buffered pipeline (2 stages) overlaps global loads
//    with MMA and bypasses L1 for the fills.
// Math unchanged: 3xTF32-compensated mma.sync (fp32-accurate).

namespace seps {

constexpr int NA = 8;
constexpr int NE = 4096;

__device__ float g_h1[(size_t)NA * NE * 1024];
__device__ float g_h2[(size_t)NA * NE * 1024];

__device__ __forceinline__ float tf32_hi(float x) {
    uint32_t r;
    asm("cvt.rna.tf32.f32 %0, %1;" : "=r"(r) : "f"(x));
    return __uint_as_float(r);
}

__device__ __forceinline__ void mma8(float* c, const uint32_t* a, const uint32_t* b) {
    asm volatile(
        "mma.sync.aligned.m16n8k8.row.col.f32.tf32.tf32.f32 "
        "{%0,%1,%2,%3}, {%4,%5,%6,%7}, {%8,%9}, {%0,%1,%2,%3};"
        : "+f"(c[0]), "+f"(c[1]), "+f"(c[2]), "+f"(c[3])
        : "r"(a[0]), "r"(a[1]), "r"(a[2]), "r"(a[3]),
          "r"(b[0]), "r"(b[1]));
}

__device__ __forceinline__ void cp_async16(void* smem_dst, const void* gmem_src) {
    uint32_t s;
    asm("{ .reg .u64 t; cvta.to.shared.u64 t, %1; cvt.u32.u64 %0, t; }"
        : "=r"(s) : "l"(smem_dst));
    asm volatile("cp.async.cg.shared.global [%0], [%1], 16;" :: "r"(s), "l"(gmem_src));
}
__device__ __forceinline__ void cp_async_commit() {
    asm volatile("cp.async.commit_group;");
}
template<int N>
__device__ __forceinline__ void cp_async_wait() {
    asm volatile("cp.async.wait_group %0;" :: "n"(N));
}

// CTA tile: 128(M) x 128(N), KT=16, 8 warps each 32x64 via m16n8k8.
template<int K, int N, bool RELU>
__global__ __launch_bounds__(256, 2)
void gemm3x_kernel(const float* __restrict__ X, const float* __restrict__ W,
                   const float* __restrict__ bias,
                   const int* __restrict__ sidx,
                   float* __restrict__ Y)
{
    constexpr int KT  = 16;
    constexpr int AS  = KT + 4;    // A smem stride (floats); row = 80B (16B-mult)
    constexpr int BSD = 128 + 4;   // B smem stride (floats); row = 528B (16B-mult)
    constexpr int NT  = K / KT;    // number of K tiles

    __shared__ float sA[2][128 * AS];
    __shared__ float sB[2][KT * BSD];

    const int tid  = threadIdx.x;
    const int lane = tid & 31;
    const int warp = tid >> 5;
    const int g = lane >> 2;
    const int t = lane & 3;
    const int wm = (warp & 3) * 32;
    const int wn = (warp >> 2) * 64;

    const int agent = blockIdx.z;
    const int m0 = blockIdx.y * 128;
    const int n0 = blockIdx.x * 128;
    const int s = sidx[agent] & 3;

    const float* Xa = X    + (size_t)agent * NE * K;
    const float* Ws = W    + (size_t)s * K * N;
    const float* bs = bias + (size_t)s * N;
    float*       Ya = Y    + (size_t)agent * NE * N;

    float acc[2][8][4];
    #pragma unroll
    for (int mi = 0; mi < 2; ++mi)
        #pragma unroll
        for (int ni = 0; ni < 8; ++ni)
            #pragma unroll
            for (int j = 0; j < 4; ++j) acc[mi][ni][j] = 0.f;

    // Load mapping (256 threads; 2 passes for A rows, 2 passes for B rows).
    const int ar  = tid >> 2;          // 0..63 (+64)
    const int ac  = (tid & 3) * 4;     // {0,4,8,12}
    const int brr = tid >> 5;          // 0..7 (+8)
    const int bc  = lane * 4;          // 0..124

    auto issue_stage = [&](int kt, int buf) {
        #pragma unroll
        for (int p = 0; p < 2; ++p) {
            cp_async16(&sA[buf][(ar + p * 64) * AS + ac],
                       Xa + (size_t)(m0 + ar + p * 64) * K + kt + ac);
            cp_async16(&sB[buf][(brr + p * 8) * BSD + bc],
                       Ws + (size_t)(kt + brr + p * 8) * N + n0 + bc);
        }
        cp_async_commit();
    };

    issue_stage(0, 0);

    #pragma unroll 1
    for (int ti = 0; ti < NT; ++ti) {
        if (ti + 1 < NT) {
            issue_stage((ti + 1) * KT, (ti + 1) & 1);
            cp_async_wait<1>();
        } else {
            cp_async_wait<0>();
        }
        __syncthreads();   // stage ti visible to all warps

        const float* cA = sA[ti & 1];
        const float* cB = sB[ti & 1];

        #pragma unroll
        for (int ks = 0; ks < KT / 8; ++ks) {
            // A fragments: raw fp32 from smem, split hi/lo in registers.
            uint32_t ah[2][4], al[2][4];
            #pragma unroll
            for (int mi = 0; mi < 2; ++mi) {
                const int r  = wm + mi * 16 + g;
                const int c0 = ks * 8 + t;
                float raw[4];
                raw[0] = cA[(r    ) * AS + c0    ];
                raw[1] = cA[(r + 8) * AS + c0    ];
                raw[2] = cA[(r    ) * AS + c0 + 4];
                raw[3] = cA[(r + 8) * AS + c0 + 4];
                #pragma unroll
                for (int j = 0; j < 4; ++j) {
                    float h = tf32_hi(raw[j]);
                    ah[mi][j] = __float_as_uint(h);
                    al[mi][j] = __float_as_uint(raw[j] - h);
                }
            }
            #pragma unroll
            for (int ni = 0; ni < 8; ++ni) {
                const int cc = wn + ni * 8 + g;
                const int rr = ks * 8 + t;
                float rb0 = cB[(rr    ) * BSD + cc];
                float rb1 = cB[(rr + 4) * BSD + cc];
                float h0 = tf32_hi(rb0), h1 = tf32_hi(rb1);
                uint32_t bh[2] = { __float_as_uint(h0), __float_as_uint(h1) };
                uint32_t bl[2] = { __float_as_uint(rb0 - h0), __float_as_uint(rb1 - h1) };
                #pragma unroll
                for (int mi = 0; mi < 2; ++mi) {
                    mma8(acc[mi][ni], ah[mi], bh);   // hi*hi
                    mma8(acc[mi][ni], ah[mi], bl);   // hi*lo
                    mma8(acc[mi][ni], al[mi], bh);   // lo*hi
                }
            }
        }
        __syncthreads();   // stage ti consumed; its buffer may be refilled
    }

    // Epilogue: bias (+ optional ReLU), float2 stores.
    #pragma unroll
    for (int mi = 0; mi < 2; ++mi) {
        const int r = m0 + wm + mi * 16 + g;
        #pragma unroll
        for (int ni = 0; ni < 8; ++ni) {
            const int ccol = n0 + wn + ni * 8 + 2 * t;
            const float2 bb = *reinterpret_cast<const float2*>(bs + ccol);
            float v0 = acc[mi][ni][0] + bb.x;
            float v1 = acc[mi][ni][1] + bb.y;
            float v2 = acc[mi][ni][2] + bb.x;
            float v3 = acc[mi][ni][3] + bb.y;
            if (RELU) {
                v0 = fmaxf(v0, 0.f); v1 = fmaxf(v1, 0.f);
                v2 = fmaxf(v2, 0.f); v3 = fmaxf(v3, 0.f);
            }
            *reinterpret_cast<float2*>(Ya + (size_t)(r    ) * N + ccol) = make_float2(v0, v1);
            *reinterpret_cast<float2*>(Ya + (size_t)(r + 8) * N + ccol) = make_float2(v2, v3);
        }
    }
}

} // namespace seps

extern "C" void kernel_launch(void* const* d_in, const int* in_sizes, int n_in,
                              void* d_out, int out_size)
{
    const float* x   = (const float*)d_in[0];
    const float* W1  = (const float*)d_in[1];
    const float* b1  = (const float*)d_in[2];
    const float* W2  = (const float*)d_in[3];
    const float* b2  = (const float*)d_in[4];
    const float* W3  = (const float*)d_in[5];
    const float* b3  = (const float*)d_in[6];
    const int* sidx  = (const int*)d_in[7];
    float* out = (float*)d_out;

    float* h1 = nullptr;
    float* h2 = nullptr;
    cudaGetSymbolAddress((void**)&h1, seps::g_h1);
    cudaGetSymbolAddress((void**)&h2, seps::g_h2);

    const dim3 blk(256);
    seps::gemm3x_kernel< 256, 1024, true ><<<dim3(8, 32, 8), blk>>>(x,  W1, b1, sidx, h1);
    seps::gemm3x_kernel<1024, 1024, true ><<<dim3(8, 32, 8), blk>>>(h1, W2, b2, sidx, h2);
    seps::gemm3x_kernel<1024,  512, false><<<dim3(4, 32, 8), blk>>>(h2, W3, b3, sidx, out);
}

// round 4
// speedup vs baseline: 2.3030x; 1.7316x over previous
#include <cuda_runtime.h>
#include <cuda_bf16.h>
#include <cstdint>
#include <cstddef>

// MultiAgentSEPSNetwork: 8 agents x (4096,256)->1024->1024->512 MLP,
// per-agent net selected by seps_idx (int32, masked to [0,3]).
//
// Round 4: bf16 hi/lo 3-term compensated MMA (m16n8k16), replacing 3xTF32.
//  - Tensor work halves (k16 per MMA vs k8).
//  - All float->bf16 splitting moved OUT of the mainloop: x and weights are
//    pre-split into bf16 hi/lo planes (weights pre-packed as k-pair bf16x2
//    words = exact B-fragment register layout); intermediate activations are
//    written as hi/lo planes by the GEMM epilogue. Mainloop = LDS.32 + MMA.
//  - KT=32 (half the barriers), conflict-free smem strides (A:20w, B:136w).

namespace seps {

constexpr int NA = 8;
constexpr int NE = 4096;

// ---- device scratch (no runtime allocation allowed) ----
__device__ uint32_t g_xh [(size_t)NA * NE * 128];   // x   hi plane, [M,256] bf16 as words
__device__ uint32_t g_xl [(size_t)NA * NE * 128];
__device__ uint32_t g_w1h[(size_t)4 * 128 * 1024];  // W1 packed [S,K/2,N] words
__device__ uint32_t g_w1l[(size_t)4 * 128 * 1024];
__device__ uint32_t g_w2h[(size_t)4 * 512 * 1024];
__device__ uint32_t g_w2l[(size_t)4 * 512 * 1024];
__device__ uint32_t g_w3h[(size_t)4 * 512 * 512];
__device__ uint32_t g_w3l[(size_t)4 * 512 * 512];
__device__ uint32_t g_h1h[(size_t)NA * NE * 512];   // h1 hi plane, [M,1024] bf16
__device__ uint32_t g_h1l[(size_t)NA * NE * 512];
__device__ uint32_t g_h2h[(size_t)NA * NE * 512];
__device__ uint32_t g_h2l[(size_t)NA * NE * 512];

// Split two fp32 into packed bf16x2 hi word + lo (residual) word.
// Word layout: low 16 bits = first element (matches MMA fragment layout).
__device__ __forceinline__ void split2(float v0, float v1, uint32_t& hw, uint32_t& lw) {
    asm("cvt.rn.bf16x2.f32 %0, %1, %2;" : "=r"(hw) : "f"(v1), "f"(v0));
    float h0 = __uint_as_float(hw << 16);
    float h1 = __uint_as_float(hw & 0xFFFF0000u);
    asm("cvt.rn.bf16x2.f32 %0, %1, %2;" : "=r"(lw) : "f"(v1 - h1), "f"(v0 - h0));
}

// Element-wise split: fp32 pairs -> hi/lo planes (natural layout).
__global__ void split_act(const float2* __restrict__ in,
                          uint32_t* __restrict__ hi, uint32_t* __restrict__ lo,
                          int nwords) {
    int i = blockIdx.x * blockDim.x + threadIdx.x;
    if (i < nwords) {
        float2 v = in[i];
        uint32_t h, l;
        split2(v.x, v.y, h, l);
        hi[i] = h; lo[i] = l;
    }
}

// Weight split + k-pair repack: in [S,K,N] f32 -> word i over [S,K/2,N]:
// word = {lo: W[2kw][n], hi: W[2kw+1][n]}  (B-fragment register layout).
__global__ void split_wgt(const float* __restrict__ in,
                          uint32_t* __restrict__ hi, uint32_t* __restrict__ lo,
                          int K2, int N, int total) {
    int i = blockIdx.x * blockDim.x + threadIdx.x;
    if (i >= total) return;
    int n   = i % N;
    int rem = i / N;          // s*K2 + kw
    const float* base = in + ((size_t)rem * 2) * N + n;
    uint32_t h, l;
    split2(base[0], base[N], h, l);
    hi[i] = h; lo[i] = l;
}

__device__ __forceinline__ void mma_bf16(float* c, const uint32_t* a, const uint32_t* b) {
    asm volatile(
        "mma.sync.aligned.m16n8k16.row.col.f32.bf16.bf16.f32 "
        "{%0,%1,%2,%3}, {%4,%5,%6,%7}, {%8,%9}, {%0,%1,%2,%3};"
        : "+f"(c[0]), "+f"(c[1]), "+f"(c[2]), "+f"(c[3])
        : "r"(a[0]), "r"(a[1]), "r"(a[2]), "r"(a[3]),
          "r"(b[0]), "r"(b[1]));
}

__device__ __forceinline__ void cp_async16(void* smem_dst, const void* gmem_src) {
    uint32_t s;
    asm("{ .reg .u64 t; cvta.to.shared.u64 t, %1; cvt.u32.u64 %0, t; }"
        : "=r"(s) : "l"(smem_dst));
    asm volatile("cp.async.cg.shared.global [%0], [%1], 16;" :: "r"(s), "l"(gmem_src));
}
__device__ __forceinline__ void cp_async_commit() { asm volatile("cp.async.commit_group;"); }
template<int N>
__device__ __forceinline__ void cp_async_wait() { asm volatile("cp.async.wait_group %0;" :: "n"(N)); }

// GEMM: Y[agent] = act( A[agent] @ W[sidx[agent]] + bias )
// A planes: [NA*NE, K/2] words (bf16 hi/lo).  B planes: [S, K/2, N] packed words.
// CTA tile 128x128, KT=32, 8 warps each 32x64 via m16n8k16, double-buffered.
template<int K, int N, bool RELU, bool SPLIT_OUT>
__global__ __launch_bounds__(256, 2)
void gemm_bf16x3(const uint32_t* __restrict__ Ah, const uint32_t* __restrict__ Al,
                 const uint32_t* __restrict__ Bh, const uint32_t* __restrict__ Bl,
                 const float* __restrict__ bias, const int* __restrict__ sidx,
                 float* __restrict__ Yf,
                 uint32_t* __restrict__ Yh, uint32_t* __restrict__ Yl)
{
    constexpr int KT = 32;          // k elements per stage
    constexpr int KW = KT / 2;      // 16 words per A row / B rows per stage
    constexpr int AS = KW + 4;      // A smem stride: 20 words (80B, conflict-free)
    constexpr int BS = 128 + 8;     // B smem stride: 136 words (8t+g mod 32, conflict-free)
    constexpr int NT = K / KT;
    constexpr int K2 = K / 2;

    __shared__ uint32_t sAh[2][128 * AS], sAl[2][128 * AS];
    __shared__ uint32_t sBh[2][KW * BS],  sBl[2][KW * BS];

    const int tid  = threadIdx.x;
    const int lane = tid & 31;
    const int warp = tid >> 5;
    const int g = lane >> 2;
    const int t = lane & 3;
    const int wm = (warp & 3) * 32;
    const int wn = (warp >> 2) * 64;

    const int agent = blockIdx.z;
    const int m0 = blockIdx.y * 128;
    const int n0 = blockIdx.x * 128;
    const int s = sidx[agent] & 3;

    const uint32_t* Aha = Ah + (size_t)agent * NE * K2;
    const uint32_t* Ala = Al + (size_t)agent * NE * K2;
    const uint32_t* Bhs = Bh + (size_t)s * K2 * N;
    const uint32_t* Bls = Bl + (size_t)s * K2 * N;
    const float*    bs  = bias + (size_t)s * N;

    float acc[2][8][4];
    #pragma unroll
    for (int mi = 0; mi < 2; ++mi)
        #pragma unroll
        for (int ni = 0; ni < 8; ++ni)
            #pragma unroll
            for (int j = 0; j < 4; ++j) acc[mi][ni][j] = 0.f;

    // Loader mapping (256 threads; 16B = 4 words per cp.async).
    const int ar = tid >> 2;          // A row 0..63 (+64)
    const int aw = (tid & 3) * 4;     // A word group {0,4,8,12}
    const int br = tid >> 5;          // B word-row 0..7 (+8)
    const int bw = lane * 4;          // B word col 0..124

    auto issue = [&](int kt, int buf) {
        const int kw0 = kt / 2;
        #pragma unroll
        for (int p = 0; p < 2; ++p) {
            const size_t arow = (size_t)(m0 + ar + p * 64);
            cp_async16(&sAh[buf][(ar + p * 64) * AS + aw], Aha + arow * K2 + kw0 + aw);
            cp_async16(&sAl[buf][(ar + p * 64) * AS + aw], Ala + arow * K2 + kw0 + aw);
            cp_async16(&sBh[buf][(br + p * 8) * BS + bw],
                       Bhs + (size_t)(kw0 + br + p * 8) * N + n0 + bw);
            cp_async16(&sBl[buf][(br + p * 8) * BS + bw],
                       Bls + (size_t)(kw0 + br + p * 8) * N + n0 + bw);
        }
        cp_async_commit();
    };

    issue(0, 0);

    #pragma unroll 1
    for (int ti = 0; ti < NT; ++ti) {
        if (ti + 1 < NT) { issue((ti + 1) * KT, (ti + 1) & 1); cp_async_wait<1>(); }
        else             { cp_async_wait<0>(); }
        __syncthreads();

        const uint32_t* cAh = sAh[ti & 1];
        const uint32_t* cAl = sAl[ti & 1];
        const uint32_t* cBh = sBh[ti & 1];
        const uint32_t* cBl = sBl[ti & 1];

        #pragma unroll
        for (int ks = 0; ks < 2; ++ks) {              // two k16 halves per stage
            uint32_t ah[2][4], al[2][4];
            #pragma unroll
            for (int mi = 0; mi < 2; ++mi) {
                const int r = wm + mi * 16 + g;
                const int c = ks * 8 + t;
                ah[mi][0] = cAh[(r    ) * AS + c    ];
                ah[mi][1] = cAh[(r + 8) * AS + c    ];
                ah[mi][2] = cAh[(r    ) * AS + c + 4];
                ah[mi][3] = cAh[(r + 8) * AS + c + 4];
                al[mi][0] = cAl[(r    ) * AS + c    ];
                al[mi][1] = cAl[(r + 8) * AS + c    ];
                al[mi][2] = cAl[(r    ) * AS + c + 4];
                al[mi][3] = cAl[(r + 8) * AS + c + 4];
            }
            #pragma unroll
            for (int ni = 0; ni < 8; ++ni) {
                const int cc = wn + ni * 8 + g;
                const int rw = ks * 8 + t;
                uint32_t bh[2] = { cBh[rw * BS + cc], cBh[(rw + 4) * BS + cc] };
                uint32_t bl[2] = { cBl[rw * BS + cc], cBl[(rw + 4) * BS + cc] };
                #pragma unroll
                for (int mi = 0; mi < 2; ++mi) {
                    mma_bf16(acc[mi][ni], ah[mi], bh);   // hi*hi
                    mma_bf16(acc[mi][ni], al[mi], bh);   // lo*hi
                    mma_bf16(acc[mi][ni], ah[mi], bl);   // hi*lo
                }
            }
        }
        __syncthreads();
    }

    // Epilogue: bias (+ReLU); either fp32 out or split hi/lo bf16 planes.
    float*    Yfa = SPLIT_OUT ? nullptr : (Yf + (size_t)agent * NE * N);
    uint32_t* Yha = SPLIT_OUT ? (Yh + (size_t)agent * NE * (N / 2)) : nullptr;
    uint32_t* Yla = SPLIT_OUT ? (Yl + (size_t)agent * NE * (N / 2)) : nullptr;

    #pragma unroll
    for (int mi = 0; mi < 2; ++mi) {
        const int r = m0 + wm + mi * 16 + g;
        #pragma unroll
        for (int ni = 0; ni < 8; ++ni) {
            const int ccol = n0 + wn + ni * 8 + 2 * t;
            const float2 bb = *reinterpret_cast<const float2*>(bs + ccol);
            float v0 = acc[mi][ni][0] + bb.x;
            float v1 = acc[mi][ni][1] + bb.y;
            float v2 = acc[mi][ni][2] + bb.x;
            float v3 = acc[mi][ni][3] + bb.y;
            if (RELU) {
                v0 = fmaxf(v0, 0.f); v1 = fmaxf(v1, 0.f);
                v2 = fmaxf(v2, 0.f); v3 = fmaxf(v3, 0.f);
            }
            if (SPLIT_OUT) {
                uint32_t h, l;
                split2(v0, v1, h, l);
                Yha[(size_t)(r    ) * (N / 2) + ccol / 2] = h;
                Yla[(size_t)(r    ) * (N / 2) + ccol / 2] = l;
                split2(v2, v3, h, l);
                Yha[(size_t)(r + 8) * (N / 2) + ccol / 2] = h;
                Yla[(size_t)(r + 8) * (N / 2) + ccol / 2] = l;
            } else {
                *reinterpret_cast<float2*>(Yfa + (size_t)(r    ) * N + ccol) = make_float2(v0, v1);
                *reinterpret_cast<float2*>(Yfa + (size_t)(r + 8) * N + ccol) = make_float2(v2, v3);
            }
        }
    }
}

} // namespace seps

extern "C" void kernel_launch(void* const* d_in, const int* in_sizes, int n_in,
                              void* d_out, int out_size)
{
    using namespace seps;
    const float* x   = (const float*)d_in[0];
    const float* W1  = (const float*)d_in[1];
    const float* b1  = (const float*)d_in[2];
    const float* W2  = (const float*)d_in[3];
    const float* b2  = (const float*)d_in[4];
    const float* W3  = (const float*)d_in[5];
    const float* b3  = (const float*)d_in[6];
    const int* sidx  = (const int*)d_in[7];
    float* out = (float*)d_out;

    uint32_t *xh, *xl, *w1h, *w1l, *w2h, *w2l, *w3h, *w3l, *h1h, *h1l, *h2h, *h2l;
    cudaGetSymbolAddress((void**)&xh,  g_xh);  cudaGetSymbolAddress((void**)&xl,  g_xl);
    cudaGetSymbolAddress((void**)&w1h, g_w1h); cudaGetSymbolAddress((void**)&w1l, g_w1l);
    cudaGetSymbolAddress((void**)&w2h, g_w2h); cudaGetSymbolAddress((void**)&w2l, g_w2l);
    cudaGetSymbolAddress((void**)&w3h, g_w3h); cudaGetSymbolAddress((void**)&w3l, g_w3l);
    cudaGetSymbolAddress((void**)&h1h, g_h1h); cudaGetSymbolAddress((void**)&h1l, g_h1l);
    cudaGetSymbolAddress((void**)&h2h, g_h2h); cudaGetSymbolAddress((void**)&h2l, g_h2l);

    // Pre-pass splits (cheap, HBM-bound, ~15us total).
    {
        int nx = NA * NE * 128;   // fp32 pairs in x
        split_act<<<(nx + 255) / 256, 256>>>((const float2*)x, xh, xl, nx);
        int n1 = 4 * 128 * 1024;
        split_wgt<<<(n1 + 255) / 256, 256>>>(W1, w1h, w1l, 128, 1024, n1);
        int n2 = 4 * 512 * 1024;
        split_wgt<<<(n2 + 255) / 256, 256>>>(W2, w2h, w2l, 512, 1024, n2);
        int n3 = 4 * 512 * 512;
        split_wgt<<<(n3 + 255) / 256, 256>>>(W3, w3h, w3l, 512, 512, n3);
    }

    const dim3 blk(256);
    gemm_bf16x3< 256, 1024, true,  true ><<<dim3(8, 32, 8), blk>>>(xh,  xl,  w1h, w1l, b1, sidx, nullptr, h1h, h1l);
    gemm_bf16x3<1024, 1024, true,  true ><<<dim3(8, 32, 8), blk>>>(h1h, h1l, w2h, w2l, b2, sidx, nullptr, h2h, h2l);
    gemm_bf16x3<1024,  512, false, false><<<dim3(4, 32, 8), blk>>>(h2h, h2l, w3h, w3l, b3, sidx, out, nullptr, nullptr);
}

// round 6
// speedup vs baseline: 2.3138x; 1.0047x over previous
#include <cuda_runtime.h>
#include <cuda_bf16.h>
#include <cstdint>
#include <cstddef>

// MultiAgentSEPSNetwork: 8 agents x (4096,256)->1024->1024->512 MLP,
// per-agent net via seps_idx (int32 &3).
//
// Round 6 (tcgen05 unavailable: harness lowers via compute_103 PTX, 'a'-only
// features rejected by ptxas). Optimized mma.sync path instead:
//  - ldmatrix.x4 fragment loads (4x fewer L1tex wavefronts than scalar LDS)
//    with B pre-transposed to [S][N][K2] planes.
//  - Term-major MMA ordering (hh*16, lh*16, hl*16 per k16) -> accumulator
//    RAW reuse distance 16 MMAs, hides HMMA latency.
// Math: bf16 hi/lo 3-term compensated m16n8k16, fp32 accum (rel_err ~1e-5).

namespace seps {

constexpr int NA = 8;
constexpr int NE = 4096;

// ---- persistent device scratch ----
__device__ uint32_t g_xh [(size_t)NA * NE * 128];    // x planes [M][K2]
__device__ uint32_t g_xl [(size_t)NA * NE * 128];
__device__ uint32_t g_w1h[(size_t)4 * 1024 * 128];   // W^T planes [S][N][K2]
__device__ uint32_t g_w1l[(size_t)4 * 1024 * 128];
__device__ uint32_t g_w2h[(size_t)4 * 1024 * 512];
__device__ uint32_t g_w2l[(size_t)4 * 1024 * 512];
__device__ uint32_t g_w3h[(size_t)4 * 512 * 512];
__device__ uint32_t g_w3l[(size_t)4 * 512 * 512];
__device__ uint32_t g_h1h[(size_t)NA * NE * 512];    // h planes [M][K2]
__device__ uint32_t g_h1l[(size_t)NA * NE * 512];
__device__ uint32_t g_h2h[(size_t)NA * NE * 512];
__device__ uint32_t g_h2l[(size_t)NA * NE * 512];

__device__ __forceinline__ uint32_t smem_u32(const void* p) {
    uint32_t a;
    asm("{ .reg .u64 t; cvta.to.shared.u64 t, %1; cvt.u32.u64 %0, t; }" : "=r"(a) : "l"(p));
    return a;
}
__device__ __forceinline__ void split2(float v0, float v1, uint32_t& hw, uint32_t& lw) {
    asm("cvt.rn.bf16x2.f32 %0, %1, %2;" : "=r"(hw) : "f"(v1), "f"(v0));
    float h0 = __uint_as_float(hw << 16);
    float h1 = __uint_as_float(hw & 0xFFFF0000u);
    asm("cvt.rn.bf16x2.f32 %0, %1, %2;" : "=r"(lw) : "f"(v1 - h1), "f"(v0 - h0));
}
__device__ __forceinline__ void cp_async16(uint32_t dst, const void* src) {
    asm volatile("cp.async.cg.shared.global [%0], [%1], 16;" :: "r"(dst), "l"(src));
}
__device__ __forceinline__ void cp_commit() { asm volatile("cp.async.commit_group;"); }
template<int N> __device__ __forceinline__ void cp_wait() {
    asm volatile("cp.async.wait_group %0;" :: "n"(N));
}
__device__ __forceinline__ void mma_bf16(float* c, const uint32_t* a, const uint32_t* b) {
    asm volatile(
        "mma.sync.aligned.m16n8k16.row.col.f32.bf16.bf16.f32 "
        "{%0,%1,%2,%3}, {%4,%5,%6,%7}, {%8,%9}, {%0,%1,%2,%3};"
        : "+f"(c[0]), "+f"(c[1]), "+f"(c[2]), "+f"(c[3])
        : "r"(a[0]), "r"(a[1]), "r"(a[2]), "r"(a[3]),
          "r"(b[0]), "r"(b[1]));
}
__device__ __forceinline__ void ldsm_x4(uint32_t& r0, uint32_t& r1, uint32_t& r2,
                                        uint32_t& r3, uint32_t addr) {
    asm volatile("ldmatrix.sync.aligned.m8n8.x4.shared.b16 {%0,%1,%2,%3}, [%4];"
                 : "=r"(r0), "=r"(r1), "=r"(r2), "=r"(r3) : "r"(addr));
}

// ---- prepass ----
__global__ void split_act(const float2* __restrict__ in,
                          uint32_t* __restrict__ hi, uint32_t* __restrict__ lo, int n) {
    int i = blockIdx.x * blockDim.x + threadIdx.x;
    if (i < n) { float2 v = in[i]; uint32_t h, l; split2(v.x, v.y, h, l); hi[i] = h; lo[i] = l; }
}
// W [S,K,N] f32 -> transposed planes [S,N,K2]; word = {k=2kw (lo16), k=2kw+1 (hi16)}.
__global__ void split_wgt_t(const float* __restrict__ in,
                            uint32_t* __restrict__ hi, uint32_t* __restrict__ lo,
                            int K2, int N, int total) {
    int i = blockIdx.x * blockDim.x + threadIdx.x;
    if (i >= total) return;
    int kw = i % K2;
    int n  = (i / K2) % N;
    int s  = i / (K2 * N);
    const float* base = in + ((size_t)s * (2 * K2) + 2 * kw) * N + n;
    uint32_t h, l;
    split2(base[0], base[N], h, l);
    hi[i] = h; lo[i] = l;
}

// ---- GEMM: CTA 128x128, KT=32, 8 warps each 32x64, double-buffered cp.async ----
// A planes [agent][M][K2]; B planes [S][NOUT][K2] (both k-word-major rows).
template<int K, int NOUT, bool RELU, bool SPLIT_OUT>
__global__ __launch_bounds__(256, 2)
void gemm_bf16x3(const uint32_t* __restrict__ Ah, const uint32_t* __restrict__ Al,
                 const uint32_t* __restrict__ Bh, const uint32_t* __restrict__ Bl,
                 const float* __restrict__ bias, const int* __restrict__ sidx,
                 float* __restrict__ Yf,
                 uint32_t* __restrict__ Yh, uint32_t* __restrict__ Yl)
{
    constexpr int KT = 32;                 // k elements per stage
    constexpr int KW = KT / 2;             // 16 words per row per stage
    constexpr int ST = 20;                 // smem row stride (words): LDSM conflict-free
    constexpr int NT = K / KT;
    constexpr int K2 = K / 2;
    constexpr int BUFW = 128 * ST;         // words per buffer (2560) = 10240 B

    __shared__ uint32_t sAh[2][BUFW], sAl[2][BUFW];
    __shared__ uint32_t sBh[2][BUFW], sBl[2][BUFW];

    const int tid  = threadIdx.x;
    const int lane = tid & 31;
    const int warp = tid >> 5;
    const int g = lane >> 2;
    const int t = lane & 3;
    const int wm = (warp & 3) * 32;        // warp M offset
    const int wn = (warp >> 2) * 64;       // warp N offset

    const int agent = blockIdx.z;
    const int m0 = blockIdx.y * 128;
    const int n0 = blockIdx.x * 128;
    const int s = sidx[agent] & 3;

    const uint32_t* Aha = Ah + (size_t)agent * NE * K2;
    const uint32_t* Ala = Al + (size_t)agent * NE * K2;
    const uint32_t* Bhs = Bh + (size_t)s * NOUT * K2;
    const uint32_t* Bls = Bl + (size_t)s * NOUT * K2;
    const float*    bs  = bias + (size_t)s * NOUT;

    const uint32_t aH = smem_u32(sAh), aL = smem_u32(sAl);
    const uint32_t bH = smem_u32(sBh), bL = smem_u32(sBl);

    float acc[2][8][4];
    #pragma unroll
    for (int mi = 0; mi < 2; ++mi)
        #pragma unroll
        for (int ni = 0; ni < 8; ++ni)
            #pragma unroll
            for (int j = 0; j < 4; ++j) acc[mi][ni][j] = 0.f;

    auto issue = [&](int ti, int buf) {
        const int kw0 = ti * KW;
        const uint32_t bo = (uint32_t)buf * (BUFW * 4);
        #pragma unroll
        for (int p = 0; p < 2; ++p) {
            const int idx = p * 256 + tid;          // 0..511
            const int row = idx >> 2;
            const int kg  = (idx & 3) * 4;
            const uint32_t so = (uint32_t)(row * ST + kg) * 4;
            cp_async16(aH + bo + so, Aha + (size_t)(m0 + row) * K2 + kw0 + kg);
            cp_async16(aL + bo + so, Ala + (size_t)(m0 + row) * K2 + kw0 + kg);
            cp_async16(bH + bo + so, Bhs + (size_t)(n0 + row) * K2 + kw0 + kg);
            cp_async16(bL + bo + so, Bls + (size_t)(n0 + row) * K2 + kw0 + kg);
        }
        cp_commit();
    };

    issue(0, 0);

    // LDSM lane addressing (byte offsets within a buffer).
    const uint32_t a_row = (uint32_t)(wm + (lane & 15));
    const uint32_t a_kw  = (uint32_t)((lane >> 4) << 2);
    const uint32_t b_row = (uint32_t)(wn + ((lane >> 4) << 3) + (lane & 7));
    const uint32_t b_kw  = (uint32_t)(((lane >> 3) & 1) << 2);

    #pragma unroll 1
    for (int ti = 0; ti < NT; ++ti) {
        if (ti + 1 < NT) { issue(ti + 1, (ti + 1) & 1); cp_wait<1>(); }
        else             { cp_wait<0>(); }
        __syncthreads();

        const uint32_t bo = (uint32_t)(ti & 1) * (BUFW * 4);

        #pragma unroll
        for (int ks = 0; ks < 2; ++ks) {
            const uint32_t kso = (uint32_t)(ks * 8);
            // A fragments: 2 mi x 4 regs x {hi,lo}
            uint32_t fAh[2][4], fAl[2][4];
            #pragma unroll
            for (int mi = 0; mi < 2; ++mi) {
                const uint32_t off = bo + ((a_row + mi * 16) * ST + kso + a_kw) * 4;
                ldsm_x4(fAh[mi][0], fAh[mi][1], fAh[mi][2], fAh[mi][3], aH + off);
                ldsm_x4(fAl[mi][0], fAl[mi][1], fAl[mi][2], fAl[mi][3], aL + off);
            }
            // B fragments: 8 ni x 2 regs x {hi,lo}; x4 covers an ni pair
            uint32_t fBh[8][2], fBl[8][2];
            #pragma unroll
            for (int np = 0; np < 4; ++np) {
                const uint32_t off = bo + ((b_row + np * 16) * ST + kso + b_kw) * 4;
                ldsm_x4(fBh[2*np][0], fBh[2*np][1], fBh[2*np+1][0], fBh[2*np+1][1], bH + off);
                ldsm_x4(fBl[2*np][0], fBl[2*np][1], fBl[2*np+1][0], fBl[2*np+1][1], bL + off);
            }
            // Term-major MMA: same-acc reuse distance = 16 MMAs.
            #pragma unroll
            for (int ni = 0; ni < 8; ++ni)
                #pragma unroll
                for (int mi = 0; mi < 2; ++mi)
                    mma_bf16(acc[mi][ni], fAh[mi], fBh[ni]);   // hi*hi
            #pragma unroll
            for (int ni = 0; ni < 8; ++ni)
                #pragma unroll
                for (int mi = 0; mi < 2; ++mi)
                    mma_bf16(acc[mi][ni], fAl[mi], fBh[ni]);   // lo*hi
            #pragma unroll
            for (int ni = 0; ni < 8; ++ni)
                #pragma unroll
                for (int mi = 0; mi < 2; ++mi)
                    mma_bf16(acc[mi][ni], fAh[mi], fBl[ni]);   // hi*lo
        }
        __syncthreads();
    }

    // ---- epilogue ----
    float*    Yfa = SPLIT_OUT ? nullptr : (Yf + (size_t)agent * NE * NOUT);
    uint32_t* Yha = SPLIT_OUT ? (Yh + (size_t)agent * NE * (NOUT / 2)) : nullptr;
    uint32_t* Yla = SPLIT_OUT ? (Yl + (size_t)agent * NE * (NOUT / 2)) : nullptr;

    #pragma unroll
    for (int mi = 0; mi < 2; ++mi) {
        const int r = m0 + wm + mi * 16 + g;
        #pragma unroll
        for (int ni = 0; ni < 8; ++ni) {
            const int ccol = n0 + wn + ni * 8 + 2 * t;
            const float2 bb = *reinterpret_cast<const float2*>(bs + ccol);
            float v0 = acc[mi][ni][0] + bb.x;
            float v1 = acc[mi][ni][1] + bb.y;
            float v2 = acc[mi][ni][2] + bb.x;
            float v3 = acc[mi][ni][3] + bb.y;
            if (RELU) {
                v0 = fmaxf(v0, 0.f); v1 = fmaxf(v1, 0.f);
                v2 = fmaxf(v2, 0.f); v3 = fmaxf(v3, 0.f);
            }
            if (SPLIT_OUT) {
                uint32_t h, l;
                split2(v0, v1, h, l);
                Yha[(size_t)(r    ) * (NOUT / 2) + ccol / 2] = h;
                Yla[(size_t)(r    ) * (NOUT / 2) + ccol / 2] = l;
                split2(v2, v3, h, l);
                Yha[(size_t)(r + 8) * (NOUT / 2) + ccol / 2] = h;
                Yla[(size_t)(r + 8) * (NOUT / 2) + ccol / 2] = l;
            } else {
                *reinterpret_cast<float2*>(Yfa + (size_t)(r    ) * NOUT + ccol) = make_float2(v0, v1);
                *reinterpret_cast<float2*>(Yfa + (size_t)(r + 8) * NOUT + ccol) = make_float2(v2, v3);
            }
        }
    }
}

} // namespace seps

extern "C" void kernel_launch(void* const* d_in, const int* in_sizes, int n_in,
                              void* d_out, int out_size)
{
    using namespace seps;
    const float* x   = (const float*)d_in[0];
    const float* W1  = (const float*)d_in[1];
    const float* b1  = (const float*)d_in[2];
    const float* W2  = (const float*)d_in[3];
    const float* b2  = (const float*)d_in[4];
    const float* W3  = (const float*)d_in[5];
    const float* b3  = (const float*)d_in[6];
    const int* sidx  = (const int*)d_in[7];
    float* out = (float*)d_out;

    uint32_t *xh, *xl, *w1h, *w1l, *w2h, *w2l, *w3h, *w3l, *h1h, *h1l, *h2h, *h2l;
    cudaGetSymbolAddress((void**)&xh,  g_xh);  cudaGetSymbolAddress((void**)&xl,  g_xl);
    cudaGetSymbolAddress((void**)&w1h, g_w1h); cudaGetSymbolAddress((void**)&w1l, g_w1l);
    cudaGetSymbolAddress((void**)&w2h, g_w2h); cudaGetSymbolAddress((void**)&w2l, g_w2l);
    cudaGetSymbolAddress((void**)&w3h, g_w3h); cudaGetSymbolAddress((void**)&w3l, g_w3l);
    cudaGetSymbolAddress((void**)&h1h, g_h1h); cudaGetSymbolAddress((void**)&h1l, g_h1l);
    cudaGetSymbolAddress((void**)&h2h, g_h2h); cudaGetSymbolAddress((void**)&h2l, g_h2l);

    // prepass: split x; split+transpose weights into [S][N][K2] planes
    {
        int nx = NA * NE * 128;
        split_act<<<(nx + 255) / 256, 256>>>((const float2*)x, xh, xl, nx);
        int n1 = 4 * 1024 * 128;
        split_wgt_t<<<(n1 + 255) / 256, 256>>>(W1, w1h, w1l, 128, 1024, n1);
        int n2 = 4 * 1024 * 512;
        split_wgt_t<<<(n2 + 255) / 256, 256>>>(W2, w2h, w2l, 512, 1024, n2);
        int n3 = 4 * 512 * 512;
        split_wgt_t<<<(n3 + 255) / 256, 256>>>(W3, w3h, w3l, 512, 512, n3);
    }

    const dim3 blk(256);
    gemm_bf16x3< 256, 1024, true,  true ><<<dim3(8, 32, 8), blk>>>(xh,  xl,  w1h, w1l, b1, sidx, nullptr, h1h, h1l);
    gemm_bf16x3<1024, 1024, true,  true ><<<dim3(8, 32, 8), blk>>>(h1h, h1l, w2h, w2l, b2, sidx, nullptr, h2h, h2l);
    gemm_bf16x3<1024,  512, false, false><<<dim3(4, 32, 8), blk>>>(h2h, h2l, w3h, w3l, b3, sidx, out, nullptr, nullptr);
}

// round 7
// speedup vs baseline: 3.2666x; 1.4118x over previous
#include <cuda_runtime.h>
#include <cuda_fp16.h>
#include <cstdint>
#include <cstddef>

// MultiAgentSEPSNetwork: 8 agents x (4096,256)->1024->1024->512 MLP,
// per-agent net via seps_idx (int32 &3).
//
// Round 7: mainloop is HMMA-throughput-bound (R6 proved schedule-insensitive),
// so reduce MMA count: fp16 2-term compensation replaces bf16 3-term.
//   A = ah + al (fp16 hi + fp16 residual, ~22 bits) ; B = fp16(b) (~12 bits).
//   y = ah@bh + al@bh  -> per-layer rel err ~1.4e-4, total ~2.5e-4 (<1e-3).
// 2/3 the MMAs of R6; B smem/global traffic halves.

namespace seps {

constexpr int NA = 8;
constexpr int NE = 4096;

// ---- persistent device scratch ----
__device__ uint32_t g_xh [(size_t)NA * NE * 128];    // x fp16 planes [M][K2]
__device__ uint32_t g_xl [(size_t)NA * NE * 128];
__device__ uint32_t g_w1h[(size_t)4 * 1024 * 128];   // W^T fp16 plane [S][N][K2]
__device__ uint32_t g_w2h[(size_t)4 * 1024 * 512];
__device__ uint32_t g_w3h[(size_t)4 * 512 * 512];
__device__ uint32_t g_h1h[(size_t)NA * NE * 512];    // h fp16 planes [M][K2]
__device__ uint32_t g_h1l[(size_t)NA * NE * 512];
__device__ uint32_t g_h2h[(size_t)NA * NE * 512];
__device__ uint32_t g_h2l[(size_t)NA * NE * 512];

__device__ __forceinline__ uint32_t smem_u32(const void* p) {
    uint32_t a;
    asm("{ .reg .u64 t; cvta.to.shared.u64 t, %1; cvt.u32.u64 %0, t; }" : "=r"(a) : "l"(p));
    return a;
}
// fp16 hi/lo split of a float pair -> packed f16x2 words.
__device__ __forceinline__ void split2h(float v0, float v1, uint32_t& hw, uint32_t& lw) {
    __half h0 = __float2half_rn(v0), h1 = __float2half_rn(v1);
    hw = (uint32_t)__half_as_ushort(h0) | ((uint32_t)__half_as_ushort(h1) << 16);
    float r0 = v0 - __half2float(h0), r1 = v1 - __half2float(h1);
    __half l0 = __float2half_rn(r0), l1 = __float2half_rn(r1);
    lw = (uint32_t)__half_as_ushort(l0) | ((uint32_t)__half_as_ushort(l1) << 16);
}
__device__ __forceinline__ uint32_t pack2h(float v0, float v1) {
    __half h0 = __float2half_rn(v0), h1 = __float2half_rn(v1);
    return (uint32_t)__half_as_ushort(h0) | ((uint32_t)__half_as_ushort(h1) << 16);
}
__device__ __forceinline__ void cp_async16(uint32_t dst, const void* src) {
    asm volatile("cp.async.cg.shared.global [%0], [%1], 16;" :: "r"(dst), "l"(src));
}
__device__ __forceinline__ void cp_commit() { asm volatile("cp.async.commit_group;"); }
template<int N> __device__ __forceinline__ void cp_wait() {
    asm volatile("cp.async.wait_group %0;" :: "n"(N));
}
__device__ __forceinline__ void mma_f16(float* c, const uint32_t* a, const uint32_t* b) {
    asm volatile(
        "mma.sync.aligned.m16n8k16.row.col.f32.f16.f16.f32 "
        "{%0,%1,%2,%3}, {%4,%5,%6,%7}, {%8,%9}, {%0,%1,%2,%3};"
        : "+f"(c[0]), "+f"(c[1]), "+f"(c[2]), "+f"(c[3])
        : "r"(a[0]), "r"(a[1]), "r"(a[2]), "r"(a[3]),
          "r"(b[0]), "r"(b[1]));
}
__device__ __forceinline__ void ldsm_x4(uint32_t& r0, uint32_t& r1, uint32_t& r2,
                                        uint32_t& r3, uint32_t addr) {
    asm volatile("ldmatrix.sync.aligned.m8n8.x4.shared.b16 {%0,%1,%2,%3}, [%4];"
                 : "=r"(r0), "=r"(r1), "=r"(r2), "=r"(r3) : "r"(addr));
}

// ---- prepass ----
__global__ void split_act(const float2* __restrict__ in,
                          uint32_t* __restrict__ hi, uint32_t* __restrict__ lo, int n) {
    int i = blockIdx.x * blockDim.x + threadIdx.x;
    if (i < n) { float2 v = in[i]; uint32_t h, l; split2h(v.x, v.y, h, l); hi[i] = h; lo[i] = l; }
}
// W [S,K,N] f32 -> transposed fp16 plane [S,N,K2]; word = {k=2kw, k=2kw+1}.
__global__ void pack_wgt_t(const float* __restrict__ in,
                           uint32_t* __restrict__ hi, int K2, int N, int total) {
    int i = blockIdx.x * blockDim.x + threadIdx.x;
    if (i >= total) return;
    int kw = i % K2;
    int n  = (i / K2) % N;
    int s  = i / (K2 * N);
    const float* base = in + ((size_t)s * (2 * K2) + 2 * kw) * N + n;
    hi[i] = pack2h(base[0], base[N]);
}

// ---- GEMM: CTA 128x128, KT=32, 8 warps each 32x64, double-buffered cp.async ----
template<int K, int NOUT, bool RELU, bool SPLIT_OUT>
__global__ __launch_bounds__(256, 2)
void gemm_f16x2(const uint32_t* __restrict__ Ah, const uint32_t* __restrict__ Al,
                const uint32_t* __restrict__ Bh,
                const float* __restrict__ bias, const int* __restrict__ sidx,
                float* __restrict__ Yf,
                uint32_t* __restrict__ Yh, uint32_t* __restrict__ Yl)
{
    constexpr int KT = 32;
    constexpr int KW = KT / 2;
    constexpr int ST = 20;                 // smem row stride (words)
    constexpr int NT = K / KT;
    constexpr int K2 = K / 2;
    constexpr int BUFW = 128 * ST;

    __shared__ uint32_t sAh[2][BUFW], sAl[2][BUFW], sBh[2][BUFW];

    const int tid  = threadIdx.x;
    const int lane = tid & 31;
    const int warp = tid >> 5;
    const int g = lane >> 2;
    const int t = lane & 3;
    const int wm = (warp & 3) * 32;
    const int wn = (warp >> 2) * 64;

    const int agent = blockIdx.z;
    const int m0 = blockIdx.y * 128;
    const int n0 = blockIdx.x * 128;
    const int s = sidx[agent] & 3;

    const uint32_t* Aha = Ah + (size_t)agent * NE * K2;
    const uint32_t* Ala = Al + (size_t)agent * NE * K2;
    const uint32_t* Bhs = Bh + (size_t)s * NOUT * K2;
    const float*    bs  = bias + (size_t)s * NOUT;

    const uint32_t aH = smem_u32(sAh), aL = smem_u32(sAl), bH = smem_u32(sBh);

    float acc[2][8][4];
    #pragma unroll
    for (int mi = 0; mi < 2; ++mi)
        #pragma unroll
        for (int ni = 0; ni < 8; ++ni)
            #pragma unroll
            for (int j = 0; j < 4; ++j) acc[mi][ni][j] = 0.f;

    auto issue = [&](int ti, int buf) {
        const int kw0 = ti * KW;
        const uint32_t bo = (uint32_t)buf * (BUFW * 4);
        #pragma unroll
        for (int p = 0; p < 2; ++p) {
            const int idx = p * 256 + tid;          // 0..511
            const int row = idx >> 2;
            const int kg  = (idx & 3) * 4;
            const uint32_t so = (uint32_t)(row * ST + kg) * 4;
            cp_async16(aH + bo + so, Aha + (size_t)(m0 + row) * K2 + kw0 + kg);
            cp_async16(aL + bo + so, Ala + (size_t)(m0 + row) * K2 + kw0 + kg);
            cp_async16(bH + bo + so, Bhs + (size_t)(n0 + row) * K2 + kw0 + kg);
        }
        cp_commit();
    };

    issue(0, 0);

    const uint32_t a_row = (uint32_t)(wm + (lane & 15));
    const uint32_t a_kw  = (uint32_t)((lane >> 4) << 2);
    const uint32_t b_row = (uint32_t)(wn + ((lane >> 4) << 3) + (lane & 7));
    const uint32_t b_kw  = (uint32_t)(((lane >> 3) & 1) << 2);

    #pragma unroll 1
    for (int ti = 0; ti < NT; ++ti) {
        if (ti + 1 < NT) { issue(ti + 1, (ti + 1) & 1); cp_wait<1>(); }
        else             { cp_wait<0>(); }
        __syncthreads();

        const uint32_t bo = (uint32_t)(ti & 1) * (BUFW * 4);

        #pragma unroll
        for (int ks = 0; ks < 2; ++ks) {
            const uint32_t kso = (uint32_t)(ks * 8);
            uint32_t fAh[2][4], fAl[2][4];
            #pragma unroll
            for (int mi = 0; mi < 2; ++mi) {
                const uint32_t off = bo + ((a_row + mi * 16) * ST + kso + a_kw) * 4;
                ldsm_x4(fAh[mi][0], fAh[mi][1], fAh[mi][2], fAh[mi][3], aH + off);
                ldsm_x4(fAl[mi][0], fAl[mi][1], fAl[mi][2], fAl[mi][3], aL + off);
            }
            uint32_t fBh[8][2];
            #pragma unroll
            for (int np = 0; np < 4; ++np) {
                const uint32_t off = bo + ((b_row + np * 16) * ST + kso + b_kw) * 4;
                ldsm_x4(fBh[2*np][0], fBh[2*np][1], fBh[2*np+1][0], fBh[2*np+1][1], bH + off);
            }
            // Term-major: hi then lo (acc reuse distance = 16 MMAs).
            #pragma unroll
            for (int ni = 0; ni < 8; ++ni)
                #pragma unroll
                for (int mi = 0; mi < 2; ++mi)
                    mma_f16(acc[mi][ni], fAh[mi], fBh[ni]);
            #pragma unroll
            for (int ni = 0; ni < 8; ++ni)
                #pragma unroll
                for (int mi = 0; mi < 2; ++mi)
                    mma_f16(acc[mi][ni], fAl[mi], fBh[ni]);
        }
        __syncthreads();
    }

    // ---- epilogue ----
    float*    Yfa = SPLIT_OUT ? nullptr : (Yf + (size_t)agent * NE * NOUT);
    uint32_t* Yha = SPLIT_OUT ? (Yh + (size_t)agent * NE * (NOUT / 2)) : nullptr;
    uint32_t* Yla = SPLIT_OUT ? (Yl + (size_t)agent * NE * (NOUT / 2)) : nullptr;

    #pragma unroll
    for (int mi = 0; mi < 2; ++mi) {
        const int r = m0 + wm + mi * 16 + g;
        #pragma unroll
        for (int ni = 0; ni < 8; ++ni) {
            const int ccol = n0 + wn + ni * 8 + 2 * t;
            const float2 bb = *reinterpret_cast<const float2*>(bs + ccol);
            float v0 = acc[mi][ni][0] + bb.x;
            float v1 = acc[mi][ni][1] + bb.y;
            float v2 = acc[mi][ni][2] + bb.x;
            float v3 = acc[mi][ni][3] + bb.y;
            if (RELU) {
                v0 = fmaxf(v0, 0.f); v1 = fmaxf(v1, 0.f);
                v2 = fmaxf(v2, 0.f); v3 = fmaxf(v3, 0.f);
            }
            if (SPLIT_OUT) {
                uint32_t h, l;
                split2h(v0, v1, h, l);
                Yha[(size_t)(r    ) * (NOUT / 2) + ccol / 2] = h;
                Yla[(size_t)(r    ) * (NOUT / 2) + ccol / 2] = l;
                split2h(v2, v3, h, l);
                Yha[(size_t)(r + 8) * (NOUT / 2) + ccol / 2] = h;
                Yla[(size_t)(r + 8) * (NOUT / 2) + ccol / 2] = l;
            } else {
                *reinterpret_cast<float2*>(Yfa + (size_t)(r    ) * NOUT + ccol) = make_float2(v0, v1);
                *reinterpret_cast<float2*>(Yfa + (size_t)(r + 8) * NOUT + ccol) = make_float2(v2, v3);
            }
        }
    }
}

} // namespace seps

extern "C" void kernel_launch(void* const* d_in, const int* in_sizes, int n_in,
                              void* d_out, int out_size)
{
    using namespace seps;
    const float* x   = (const float*)d_in[0];
    const float* W1  = (const float*)d_in[1];
    const float* b1  = (const float*)d_in[2];
    const float* W2  = (const float*)d_in[3];
    const float* b2  = (const float*)d_in[4];
    const float* W3  = (const float*)d_in[5];
    const float* b3  = (const float*)d_in[6];
    const int* sidx  = (const int*)d_in[7];
    float* out = (float*)d_out;

    uint32_t *xh, *xl, *w1h, *w2h, *w3h, *h1h, *h1l, *h2h, *h2l;
    cudaGetSymbolAddress((void**)&xh,  g_xh);  cudaGetSymbolAddress((void**)&xl,  g_xl);
    cudaGetSymbolAddress((void**)&w1h, g_w1h);
    cudaGetSymbolAddress((void**)&w2h, g_w2h);
    cudaGetSymbolAddress((void**)&w3h, g_w3h);
    cudaGetSymbolAddress((void**)&h1h, g_h1h); cudaGetSymbolAddress((void**)&h1l, g_h1l);
    cudaGetSymbolAddress((void**)&h2h, g_h2h); cudaGetSymbolAddress((void**)&h2l, g_h2l);

    // prepass
    {
        int nx = NA * NE * 128;
        split_act<<<(nx + 255) / 256, 256>>>((const float2*)x, xh, xl, nx);
        int n1 = 4 * 1024 * 128;
        pack_wgt_t<<<(n1 + 255) / 256, 256>>>(W1, w1h, 128, 1024, n1);
        int n2 = 4 * 1024 * 512;
        pack_wgt_t<<<(n2 + 255) / 256, 256>>>(W2, w2h, 512, 1024, n2);
        int n3 = 4 * 512 * 512;
        pack_wgt_t<<<(n3 + 255) / 256, 256>>>(W3, w3h, 512, 512, n3);
    }

    const dim3 blk(256);
    gemm_f16x2< 256, 1024, true,  true ><<<dim3(8, 32, 8), blk>>>(xh,  xl,  w1h, b1, sidx, nullptr, h1h, h1l);
    gemm_f16x2<1024, 1024, true,  true ><<<dim3(8, 32, 8), blk>>>(h1h, h1l, w2h, b2, sidx, nullptr, h2h, h2l);
    gemm_f16x2<1024,  512, false, false><<<dim3(4, 32, 8), blk>>>(h2h, h2l, w3h, b3, sidx, out, nullptr, nullptr);
}

// round 8
// speedup vs baseline: 5.2276x; 1.6003x over previous
#include <cuda_runtime.h>
#include <cuda_fp16.h>
#include <cstdint>
#include <cstddef>

// MultiAgentSEPSNetwork: 8 agents x (4096,256)->1024->1024->512 MLP,
// per-agent net via seps_idx (int32 &3).
//
// Round 8: mainloop time is proportional to MMA count (R6/R7 established the
// HMMA-throughput ceiling), so run single-term fp16: A=fp16(x), B=fp16(W),
// fp32 accumulate. Calibrated error model predicts rel_err ~5e-4 (<1e-3).
// Half the MMAs and half the A-side traffic of R7.

namespace seps {

constexpr int NA = 8;
constexpr int NE = 4096;

// ---- persistent device scratch ----
__device__ uint32_t g_xh [(size_t)NA * NE * 128];    // x fp16 [M][K2] words
__device__ uint32_t g_w1h[(size_t)4 * 1024 * 128];   // W^T fp16 [S][N][K2]
__device__ uint32_t g_w2h[(size_t)4 * 1024 * 512];
__device__ uint32_t g_w3h[(size_t)4 * 512 * 512];
__device__ uint32_t g_h1h[(size_t)NA * NE * 512];    // h fp16 [M][K2]
__device__ uint32_t g_h2h[(size_t)NA * NE * 512];

__device__ __forceinline__ uint32_t smem_u32(const void* p) {
    uint32_t a;
    asm("{ .reg .u64 t; cvta.to.shared.u64 t, %1; cvt.u32.u64 %0, t; }" : "=r"(a) : "l"(p));
    return a;
}
__device__ __forceinline__ uint32_t pack2h(float v0, float v1) {
    __half h0 = __float2half_rn(v0), h1 = __float2half_rn(v1);
    return (uint32_t)__half_as_ushort(h0) | ((uint32_t)__half_as_ushort(h1) << 16);
}
__device__ __forceinline__ void cp_async16(uint32_t dst, const void* src) {
    asm volatile("cp.async.cg.shared.global [%0], [%1], 16;" :: "r"(dst), "l"(src));
}
__device__ __forceinline__ void cp_commit() { asm volatile("cp.async.commit_group;"); }
template<int N> __device__ __forceinline__ void cp_wait() {
    asm volatile("cp.async.wait_group %0;" :: "n"(N));
}
__device__ __forceinline__ void mma_f16(float* c, const uint32_t* a, const uint32_t* b) {
    asm volatile(
        "mma.sync.aligned.m16n8k16.row.col.f32.f16.f16.f32 "
        "{%0,%1,%2,%3}, {%4,%5,%6,%7}, {%8,%9}, {%0,%1,%2,%3};"
        : "+f"(c[0]), "+f"(c[1]), "+f"(c[2]), "+f"(c[3])
        : "r"(a[0]), "r"(a[1]), "r"(a[2]), "r"(a[3]),
          "r"(b[0]), "r"(b[1]));
}
__device__ __forceinline__ void ldsm_x4(uint32_t& r0, uint32_t& r1, uint32_t& r2,
                                        uint32_t& r3, uint32_t addr) {
    asm volatile("ldmatrix.sync.aligned.m8n8.x4.shared.b16 {%0,%1,%2,%3}, [%4];"
                 : "=r"(r0), "=r"(r1), "=r"(r2), "=r"(r3) : "r"(addr));
}

// ---- prepass ----
__global__ void pack_act(const float2* __restrict__ in, uint32_t* __restrict__ hi, int n) {
    int i = blockIdx.x * blockDim.x + threadIdx.x;
    if (i < n) { float2 v = in[i]; hi[i] = pack2h(v.x, v.y); }
}
// W [S,K,N] f32 -> transposed fp16 plane [S,N,K2]; word = {k=2kw, k=2kw+1}.
__global__ void pack_wgt_t(const float* __restrict__ in,
                           uint32_t* __restrict__ hi, int K2, int N, int total) {
    int i = blockIdx.x * blockDim.x + threadIdx.x;
    if (i >= total) return;
    int kw = i % K2;
    int n  = (i / K2) % N;
    int s  = i / (K2 * N);
    const float* base = in + ((size_t)s * (2 * K2) + 2 * kw) * N + n;
    hi[i] = pack2h(base[0], base[N]);
}

// ---- GEMM: CTA 128x128, KT=32, 8 warps each 32x64, double-buffered cp.async ----
template<int K, int NOUT, bool RELU, bool PACK_OUT>
__global__ __launch_bounds__(256, 2)
void gemm_f16(const uint32_t* __restrict__ Ah, const uint32_t* __restrict__ Bh,
              const float* __restrict__ bias, const int* __restrict__ sidx,
              float* __restrict__ Yf, uint32_t* __restrict__ Yh)
{
    constexpr int KT = 32;
    constexpr int KW = KT / 2;
    constexpr int ST = 20;                 // smem row stride (words)
    constexpr int NT = K / KT;
    constexpr int K2 = K / 2;
    constexpr int BUFW = 128 * ST;

    __shared__ uint32_t sAh[2][BUFW], sBh[2][BUFW];

    const int tid  = threadIdx.x;
    const int lane = tid & 31;
    const int warp = tid >> 5;
    const int g = lane >> 2;
    const int t = lane & 3;
    const int wm = (warp & 3) * 32;
    const int wn = (warp >> 2) * 64;

    const int agent = blockIdx.z;
    const int m0 = blockIdx.y * 128;
    const int n0 = blockIdx.x * 128;
    const int s = sidx[agent] & 3;

    const uint32_t* Aha = Ah + (size_t)agent * NE * K2;
    const uint32_t* Bhs = Bh + (size_t)s * NOUT * K2;
    const float*    bs  = bias + (size_t)s * NOUT;

    const uint32_t aH = smem_u32(sAh), bH = smem_u32(sBh);

    float acc[2][8][4];
    #pragma unroll
    for (int mi = 0; mi < 2; ++mi)
        #pragma unroll
        for (int ni = 0; ni < 8; ++ni)
            #pragma unroll
            for (int j = 0; j < 4; ++j) acc[mi][ni][j] = 0.f;

    auto issue = [&](int ti, int buf) {
        const int kw0 = ti * KW;
        const uint32_t bo = (uint32_t)buf * (BUFW * 4);
        #pragma unroll
        for (int p = 0; p < 2; ++p) {
            const int idx = p * 256 + tid;          // 0..511
            const int row = idx >> 2;
            const int kg  = (idx & 3) * 4;
            const uint32_t so = (uint32_t)(row * ST + kg) * 4;
            cp_async16(aH + bo + so, Aha + (size_t)(m0 + row) * K2 + kw0 + kg);
            cp_async16(bH + bo + so, Bhs + (size_t)(n0 + row) * K2 + kw0 + kg);
        }
        cp_commit();
    };

    issue(0, 0);

    const uint32_t a_row = (uint32_t)(wm + (lane & 15));
    const uint32_t a_kw  = (uint32_t)((lane >> 4) << 2);
    const uint32_t b_row = (uint32_t)(wn + ((lane >> 4) << 3) + (lane & 7));
    const uint32_t b_kw  = (uint32_t)(((lane >> 3) & 1) << 2);

    #pragma unroll 1
    for (int ti = 0; ti < NT; ++ti) {
        if (ti + 1 < NT) { issue(ti + 1, (ti + 1) & 1); cp_wait<1>(); }
        else             { cp_wait<0>(); }
        __syncthreads();

        const uint32_t bo = (uint32_t)(ti & 1) * (BUFW * 4);

        #pragma unroll
        for (int ks = 0; ks < 2; ++ks) {
            const uint32_t kso = (uint32_t)(ks * 8);
            uint32_t fA[2][4];
            #pragma unroll
            for (int mi = 0; mi < 2; ++mi) {
                const uint32_t off = bo + ((a_row + mi * 16) * ST + kso + a_kw) * 4;
                ldsm_x4(fA[mi][0], fA[mi][1], fA[mi][2], fA[mi][3], aH + off);
            }
            uint32_t fB[8][2];
            #pragma unroll
            for (int np = 0; np < 4; ++np) {
                const uint32_t off = bo + ((b_row + np * 16) * ST + kso + b_kw) * 4;
                ldsm_x4(fB[2*np][0], fB[2*np][1], fB[2*np+1][0], fB[2*np+1][1], bH + off);
            }
            #pragma unroll
            for (int ni = 0; ni < 8; ++ni)
                #pragma unroll
                for (int mi = 0; mi < 2; ++mi)
                    mma_f16(acc[mi][ni], fA[mi], fB[ni]);
        }
        __syncthreads();
    }

    // ---- epilogue ----
    float*    Yfa = PACK_OUT ? nullptr : (Yf + (size_t)agent * NE * NOUT);
    uint32_t* Yha = PACK_OUT ? (Yh + (size_t)agent * NE * (NOUT / 2)) : nullptr;

    #pragma unroll
    for (int mi = 0; mi < 2; ++mi) {
        const int r = m0 + wm + mi * 16 + g;
        #pragma unroll
        for (int ni = 0; ni < 8; ++ni) {
            const int ccol = n0 + wn + ni * 8 + 2 * t;
            const float2 bb = *reinterpret_cast<const float2*>(bs + ccol);
            float v0 = acc[mi][ni][0] + bb.x;
            float v1 = acc[mi][ni][1] + bb.y;
            float v2 = acc[mi][ni][2] + bb.x;
            float v3 = acc[mi][ni][3] + bb.y;
            if (RELU) {
                v0 = fmaxf(v0, 0.f); v1 = fmaxf(v1, 0.f);
                v2 = fmaxf(v2, 0.f); v3 = fmaxf(v3, 0.f);
            }
            if (PACK_OUT) {
                Yha[(size_t)(r    ) * (NOUT / 2) + ccol / 2] = pack2h(v0, v1);
                Yha[(size_t)(r + 8) * (NOUT / 2) + ccol / 2] = pack2h(v2, v3);
            } else {
                *reinterpret_cast<float2*>(Yfa + (size_t)(r    ) * NOUT + ccol) = make_float2(v0, v1);
                *reinterpret_cast<float2*>(Yfa + (size_t)(r + 8) * NOUT + ccol) = make_float2(v2, v3);
            }
        }
    }
}

} // namespace seps

extern "C" void kernel_launch(void* const* d_in, const int* in_sizes, int n_in,
                              void* d_out, int out_size)
{
    using namespace seps;
    const float* x   = (const float*)d_in[0];
    const float* W1  = (const float*)d_in[1];
    const float* b1  = (const float*)d_in[2];
    const float* W2  = (const float*)d_in[3];
    const float* b2  = (const float*)d_in[4];
    const float* W3  = (const float*)d_in[5];
    const float* b3  = (const float*)d_in[6];
    const int* sidx  = (const int*)d_in[7];
    float* out = (float*)d_out;

    uint32_t *xh, *w1h, *w2h, *w3h, *h1h, *h2h;
    cudaGetSymbolAddress((void**)&xh,  g_xh);
    cudaGetSymbolAddress((void**)&w1h, g_w1h);
    cudaGetSymbolAddress((void**)&w2h, g_w2h);
    cudaGetSymbolAddress((void**)&w3h, g_w3h);
    cudaGetSymbolAddress((void**)&h1h, g_h1h);
    cudaGetSymbolAddress((void**)&h2h, g_h2h);

    // prepass
    {
        int nx = NA * NE * 128;
        pack_act<<<(nx + 255) / 256, 256>>>((const float2*)x, xh, nx);
        int n1 = 4 * 1024 * 128;
        pack_wgt_t<<<(n1 + 255) / 256, 256>>>(W1, w1h, 128, 1024, n1);
        int n2 = 4 * 1024 * 512;
        pack_wgt_t<<<(n2 + 255) / 256, 256>>>(W2, w2h, 512, 1024, n2);
        int n3 = 4 * 512 * 512;
        pack_wgt_t<<<(n3 + 255) / 256, 256>>>(W3, w3h, 512, 512, n3);
    }

    const dim3 blk(256);
    gemm_f16< 256, 1024, true,  true ><<<dim3(8, 32, 8), blk>>>(xh,  w1h, b1, sidx, nullptr, h1h);
    gemm_f16<1024, 1024, true,  true ><<<dim3(8, 32, 8), blk>>>(h1h, w2h, b2, sidx, nullptr, h2h);
    gemm_f16<1024,  512, false, false><<<dim3(4, 32, 8), blk>>>(h2h, w3h, b3, sidx, out, nullptr);
}